// round 4
// baseline (speedup 1.0000x reference)
#include <cuda_runtime.h>
#include <math.h>
#include <stdint.h>

#define N_NODES 50000
#define N_EDGES 800000
#define HID     96
#define BM      128
#define WT_STRIDE 98   // floats; even (8B alignment for LDS.64), bank step 2 -> conflict-free

// Scratch (device globals; no allocation allowed)
__device__ float g_h[N_NODES * HID];
__device__ float g_aggr[N_NODES * HID];
__device__ float g_x[N_NODES * HID];
__device__ float g_t[N_NODES * HID];

__device__ __forceinline__ float gelu_exact(float x) {
    return 0.5f * x * (1.0f + erff(x * 0.7071067811865476f));
}

// MODE 0 (PRE):  A = x_feat;          out = g_h = gelu(A@W+b); also zero g_aggr rows
// MODE 1 (MID):  A = x_feat + g_aggr; out = g_t = gelu(A@W+b); also persist A into g_x
// MODE 2 (POST): A = g_t;             out = g_x + gelu(A@W+b)  (final output)
template <int MODE>
__global__ __launch_bounds__(256, 2)
void gemm_kernel(const float* __restrict__ A0,
                 const float* __restrict__ W,
                 const float* __restrict__ bias,
                 float* __restrict__ out) {
    extern __shared__ float smem[];
    float* Xs = smem;                          // BM x 96, row-major, no pad (96*4 % 8B ok)
    float* Wt = smem + BM * HID;               // 96 cols x WT_STRIDE (transposed: Wt[c][k])
    float* Bs = Wt + HID * WT_STRIDE;          // 96

    const int tid  = threadIdx.x;
    const int row0 = blockIdx.x * BM;

    // ---- load + transpose W: Wt[n*WT_STRIDE + k] = W[k*96 + n] ----
#pragma unroll
    for (int i = 0; i < 36; i++) {
        int e = tid + 256 * i;
        int k = e / HID, n = e - k * HID;
        Wt[n * WT_STRIDE + k] = W[e];
    }
    if (tid < 24) ((float4*)Bs)[tid] = ((const float4*)bias)[tid];

    // ---- load X tile (128x96 = 3072 float4, 12 per thread, coalesced) ----
#pragma unroll
    for (int i = 0; i < 12; i++) {
        int idx4 = tid + 256 * i;
        int r = idx4 / 24, c4 = idx4 - (idx4 / 24) * 24;
        int row = row0 + r;
        float4 v = make_float4(0.f, 0.f, 0.f, 0.f);
        if (row < N_NODES) {
            v = ((const float4*)(A0 + (size_t)row * HID))[c4];
            if (MODE == 1) {
                float4 a = ((const float4*)(g_aggr + (size_t)row * HID))[c4];
                v.x += a.x; v.y += a.y; v.z += a.z; v.w += a.w;
                ((float4*)(g_x + (size_t)row * HID))[c4] = v;  // persist residual-1
            }
            if (MODE == 0)
                ((float4*)(g_aggr + (size_t)row * HID))[c4] = make_float4(0.f, 0.f, 0.f, 0.f);
        }
        ((float4*)(Xs + r * HID))[c4] = v;
    }
    __syncthreads();

    // ---- compute: 8 rows x 6 cols per thread; f32x2 lanes = (even k, odd k) ----
    // acc[i][j] lanes hold partial sums over even/odd k; horizontal add at the end.
    const int tx = tid & 15;   // cols: tx + 16*j, j = 0..5
    const int ty = tid >> 4;   // rows: ty*8 + i
    unsigned long long acc[8][6];
#pragma unroll
    for (int i = 0; i < 8; i++)
#pragma unroll
        for (int j = 0; j < 6; j++) acc[i][j] = 0ULL;

    const float* xbase = &Xs[(ty * 8) * HID];
    const float* wbase = &Wt[tx * WT_STRIDE];

#pragma unroll 4
    for (int kp = 0; kp < HID / 2; kp++) {
        const int k = 2 * kp;
        unsigned long long b[6];
#pragma unroll
        for (int j = 0; j < 6; j++)
            b[j] = *(const unsigned long long*)(wbase + (16 * j) * WT_STRIDE + k);
#pragma unroll
        for (int i = 0; i < 8; i++) {
            unsigned long long a = *(const unsigned long long*)(xbase + i * HID + k);
#pragma unroll
            for (int j = 0; j < 6; j++)
                asm("fma.rn.f32x2 %0, %1, %2, %0;"
                    : "+l"(acc[i][j]) : "l"(a), "l"(b[j]));
        }
    }

    // ---- epilogue: horizontal add + bias + gelu + residual ----
#pragma unroll
    for (int i = 0; i < 8; i++) {
        int row = row0 + ty * 8 + i;
        if (row < N_NODES) {
#pragma unroll
            for (int j = 0; j < 6; j++) {
                float lo, hi;
                asm("mov.b64 {%0, %1}, %2;" : "=f"(lo), "=f"(hi) : "l"(acc[i][j]));
                int col = tx + 16 * j;
                float v = lo + hi + Bs[col];
                float g = gelu_exact(v);
                size_t o = (size_t)row * HID + col;
                if (MODE == 2) out[o] = g_x[o] + g;
                else           out[o] = g;
            }
        }
    }
}

// Edge scatter: aggr[dst] += h[src] * bases, one float4 per thread.
// bases read is perfectly coalesced (idx IS the float4 index of bases).
__global__ __launch_bounds__(256)
void edge_kernel(const float* __restrict__ bases,
                 const int* __restrict__ src,
                 const int* __restrict__ dst) {
    int idx = blockIdx.x * 256 + threadIdx.x;            // < 19.2M, fits int
    if (idx >= N_EDGES * 24) return;
    int e = idx / 24;
    int c = idx - e * 24;
    int s = src[e];
    int d = dst[e];
    float4 b  = ((const float4*)bases)[idx];
    float4 hv = ((const float4*)(g_h + (size_t)s * HID))[c];
    float4 m  = make_float4(b.x * hv.x, b.y * hv.y, b.z * hv.z, b.w * hv.w);
    float* p = g_aggr + (size_t)d * HID + c * 4;
    asm volatile("red.global.add.v4.f32 [%0], {%1, %2, %3, %4};"
                 :: "l"(p), "f"(m.x), "f"(m.y), "f"(m.z), "f"(m.w)
                 : "memory");
}

extern "C" void kernel_launch(void* const* d_in, const int* in_sizes, int n_in,
                              void* d_out, int out_size) {
    const float* x_feat = (const float*)d_in[0];
    const float* bases  = (const float*)d_in[1];
    const float* W_pre  = (const float*)d_in[2];
    const float* b_pre  = (const float*)d_in[3];
    const float* W1     = (const float*)d_in[4];
    const float* b1     = (const float*)d_in[5];
    const float* W2     = (const float*)d_in[6];
    const float* b2     = (const float*)d_in[7];
    const int*   src    = (const int*)d_in[8];
    const int*   dst    = (const int*)d_in[9];
    float* out = (float*)d_out;

    const int smem_bytes = (BM * HID + HID * WT_STRIDE + HID + 8) * sizeof(float);
    cudaFuncSetAttribute(gemm_kernel<0>, cudaFuncAttributeMaxDynamicSharedMemorySize, smem_bytes);
    cudaFuncSetAttribute(gemm_kernel<1>, cudaFuncAttributeMaxDynamicSharedMemorySize, smem_bytes);
    cudaFuncSetAttribute(gemm_kernel<2>, cudaFuncAttributeMaxDynamicSharedMemorySize, smem_bytes);

    float* g_h_p;    cudaGetSymbolAddress((void**)&g_h_p, g_h);
    float* g_t_p;    cudaGetSymbolAddress((void**)&g_t_p, g_t);

    const int gemm_grid = (N_NODES + BM - 1) / BM;   // 391
    const int edge_grid = (N_EDGES * 24 + 255) / 256;

    // 1) h = gelu(x_feat @ W_pre + b_pre); zero aggr
    gemm_kernel<0><<<gemm_grid, 256, smem_bytes>>>(x_feat, W_pre, b_pre, g_h_p);
    // 2) aggr[dst] += h[src] * bases
    edge_kernel<<<edge_grid, 256>>>(bases, src, dst);
    // 3) x = x_feat + aggr (persisted); t = gelu(x @ W1 + b1)
    gemm_kernel<1><<<gemm_grid, 256, smem_bytes>>>(x_feat, W1, b1, g_t_p);
    // 4) out = x + gelu(t @ W2 + b2)
    gemm_kernel<2><<<gemm_grid, 256, smem_bytes>>>(g_t_p, W2, b2, out);
}

// round 5
// speedup vs baseline: 1.2987x; 1.2987x over previous
#include <cuda_runtime.h>
#include <cuda_bf16.h>
#include <math.h>
#include <stdint.h>

#define N_NODES 50000
#define N_EDGES 800000
#define HID     96
#define BM      128
#define KST     100        // bf16-element stride for A/B smem tiles (conflict-free)

// smem byte offsets
#define SM_AHI  0
#define SM_ALO  25600
#define SM_BHI  51200
#define SM_BLO  70400
#define SM_BIAS 89600
#define SM_TOT  89984

// Scratch (device globals; no allocation allowed)
__device__ float g_h[N_NODES * HID];
__device__ float g_aggr[N_NODES * HID];
__device__ float g_x[N_NODES * HID];
__device__ float g_t[N_NODES * HID];

__device__ __forceinline__ float gelu_exact(float x) {
    return 0.5f * x * (1.0f + erff(x * 0.7071067811865476f));
}
__device__ __forceinline__ void bf16_split(float v, uint16_t& hi, uint16_t& lo) {
    __nv_bfloat16 h = __float2bfloat16(v);
    __nv_bfloat16 l = __float2bfloat16(v - __bfloat162float(h));
    hi = __bfloat16_as_ushort(h);
    lo = __bfloat16_as_ushort(l);
}

// MODE 0 (PRE):  A = x_feat;          out = g_h = gelu(A@W+b); also zero g_aggr rows
// MODE 1 (MID):  A = x_feat + g_aggr; out = g_t = gelu(A@W+b); also persist A into g_x
// MODE 2 (POST): A = g_t;             out = g_x + gelu(A@W+b)  (final output)
template <int MODE>
__global__ __launch_bounds__(256, 2)
void gemm_kernel(const float* __restrict__ A0,
                 const float* __restrict__ W,
                 const float* __restrict__ bias,
                 float* __restrict__ out) {
    extern __shared__ char smem[];
    uint16_t* Ahi = (uint16_t*)(smem + SM_AHI);   // [128 rows][KST k] bf16
    uint16_t* Alo = (uint16_t*)(smem + SM_ALO);
    uint16_t* Bhi = (uint16_t*)(smem + SM_BHI);   // [96 cols(n)][KST k] bf16 (W transposed)
    uint16_t* Blo = (uint16_t*)(smem + SM_BLO);
    float*    Bsm = (float*)(smem + SM_BIAS);     // 96 bias floats

    const int tid  = threadIdx.x;
    const int row0 = blockIdx.x * BM;

    // ---- W: load fp32 (coalesced), split, store transposed Bt[n][k] ----
#pragma unroll
    for (int i = 0; i < 36; i++) {
        int e = tid + 256 * i;                 // e = k*96 + n
        int k = e / HID, n = e - k * HID;
        uint16_t hi, lo;
        bf16_split(W[e], hi, lo);
        Bhi[n * KST + k] = hi;
        Blo[n * KST + k] = lo;
    }
    if (tid < 24) ((float4*)Bsm)[tid] = ((const float4*)bias)[tid];

    // ---- X tile: load fp32, MODE transform, split, store row-major bf16 ----
#pragma unroll
    for (int i = 0; i < 12; i++) {
        int idx4 = tid + 256 * i;
        int r = idx4 / 24, c4 = idx4 - (idx4 / 24) * 24;
        int row = row0 + r;
        float4 v = make_float4(0.f, 0.f, 0.f, 0.f);
        if (row < N_NODES) {
            v = ((const float4*)(A0 + (size_t)row * HID))[c4];
            if (MODE == 1) {
                float4 a = ((const float4*)(g_aggr + (size_t)row * HID))[c4];
                v.x += a.x; v.y += a.y; v.z += a.z; v.w += a.w;
                ((float4*)(g_x + (size_t)row * HID))[c4] = v;   // persist residual-1
            }
            if (MODE == 0)
                ((float4*)(g_aggr + (size_t)row * HID))[c4] = make_float4(0.f, 0.f, 0.f, 0.f);
        }
        ushort4 h4, l4;
        bf16_split(v.x, h4.x, l4.x);
        bf16_split(v.y, h4.y, l4.y);
        bf16_split(v.z, h4.z, l4.z);
        bf16_split(v.w, h4.w, l4.w);
        *(ushort4*)&Ahi[r * KST + c4 * 4] = h4;
        *(ushort4*)&Alo[r * KST + c4 * 4] = l4;
    }
    __syncthreads();

    // ---- MMA: warp w covers rows m0..m0+31, cols n0..n0+47 ----
    const int w  = tid >> 5;
    const int l  = tid & 31;
    const int m0 = (w & 3) * 32;
    const int n0 = (w >> 2) * 48;
    const int lr = l >> 2;          // 0..7
    const int lk = 2 * (l & 3);     // 0,2,4,6

    float acc[2][6][4];
#pragma unroll
    for (int mt = 0; mt < 2; mt++)
#pragma unroll
        for (int nt = 0; nt < 6; nt++)
#pragma unroll
            for (int q = 0; q < 4; q++) acc[mt][nt][q] = 0.f;

#pragma unroll
    for (int term = 0; term < 3; term++) {
        const uint16_t* Aq = (term == 1) ? Alo : Ahi;
        const uint16_t* Bq = (term == 2) ? Blo : Bhi;
#pragma unroll
        for (int ks = 0; ks < 6; ks++) {
            const int k0 = ks * 16 + lk;
            uint32_t af[2][4];
#pragma unroll
            for (int mt = 0; mt < 2; mt++) {
                int r = m0 + mt * 16 + lr;
                af[mt][0] = *(const uint32_t*)&Aq[r * KST + k0];
                af[mt][1] = *(const uint32_t*)&Aq[(r + 8) * KST + k0];
                af[mt][2] = *(const uint32_t*)&Aq[r * KST + k0 + 8];
                af[mt][3] = *(const uint32_t*)&Aq[(r + 8) * KST + k0 + 8];
            }
            uint32_t bf[6][2];
#pragma unroll
            for (int nt = 0; nt < 6; nt++) {
                int c = n0 + nt * 8 + lr;
                bf[nt][0] = *(const uint32_t*)&Bq[c * KST + k0];
                bf[nt][1] = *(const uint32_t*)&Bq[c * KST + k0 + 8];
            }
#pragma unroll
            for (int mt = 0; mt < 2; mt++)
#pragma unroll
                for (int nt = 0; nt < 6; nt++)
                    asm volatile(
                        "mma.sync.aligned.m16n8k16.row.col.f32.bf16.bf16.f32 "
                        "{%0,%1,%2,%3}, {%4,%5,%6,%7}, {%8,%9}, {%0,%1,%2,%3};"
                        : "+f"(acc[mt][nt][0]), "+f"(acc[mt][nt][1]),
                          "+f"(acc[mt][nt][2]), "+f"(acc[mt][nt][3])
                        : "r"(af[mt][0]), "r"(af[mt][1]), "r"(af[mt][2]), "r"(af[mt][3]),
                          "r"(bf[nt][0]), "r"(bf[nt][1]));
        }
    }

    // ---- epilogue straight from registers ----
#pragma unroll
    for (int mt = 0; mt < 2; mt++) {
#pragma unroll
        for (int nt = 0; nt < 6; nt++) {
            int col = n0 + nt * 8 + lk;
            float bx = Bsm[col], by = Bsm[col + 1];
            int r1 = row0 + m0 + mt * 16 + lr;
            int r2 = r1 + 8;
            if (r1 < N_NODES) {
                float gx = gelu_exact(acc[mt][nt][0] + bx);
                float gy = gelu_exact(acc[mt][nt][1] + by);
                size_t o = (size_t)r1 * HID + col;
                if (MODE == 2) {
                    float2 xv = *(const float2*)(g_x + o);
                    gx += xv.x; gy += xv.y;
                }
                *(float2*)(out + o) = make_float2(gx, gy);
            }
            if (r2 < N_NODES) {
                float gx = gelu_exact(acc[mt][nt][2] + bx);
                float gy = gelu_exact(acc[mt][nt][3] + by);
                size_t o = (size_t)r2 * HID + col;
                if (MODE == 2) {
                    float2 xv = *(const float2*)(g_x + o);
                    gx += xv.x; gy += xv.y;
                }
                *(float2*)(out + o) = make_float2(gx, gy);
            }
        }
    }
}

// Edge scatter: aggr[dst] += h[src] * bases, one float4 per thread.
__global__ __launch_bounds__(256)
void edge_kernel(const float* __restrict__ bases,
                 const int* __restrict__ src,
                 const int* __restrict__ dst) {
    int idx = blockIdx.x * 256 + threadIdx.x;
    if (idx >= N_EDGES * 24) return;
    int e = idx / 24;
    int c = idx - e * 24;
    int s = src[e];
    int d = dst[e];
    float4 b  = ((const float4*)bases)[idx];
    float4 hv = ((const float4*)(g_h + (size_t)s * HID))[c];
    float4 m  = make_float4(b.x * hv.x, b.y * hv.y, b.z * hv.z, b.w * hv.w);
    float* p = g_aggr + (size_t)d * HID + c * 4;
    asm volatile("red.global.add.v4.f32 [%0], {%1, %2, %3, %4};"
                 :: "l"(p), "f"(m.x), "f"(m.y), "f"(m.z), "f"(m.w)
                 : "memory");
}

extern "C" void kernel_launch(void* const* d_in, const int* in_sizes, int n_in,
                              void* d_out, int out_size) {
    const float* x_feat = (const float*)d_in[0];
    const float* bases  = (const float*)d_in[1];
    const float* W_pre  = (const float*)d_in[2];
    const float* b_pre  = (const float*)d_in[3];
    const float* W1     = (const float*)d_in[4];
    const float* b1     = (const float*)d_in[5];
    const float* W2     = (const float*)d_in[6];
    const float* b2     = (const float*)d_in[7];
    const int*   src    = (const int*)d_in[8];
    const int*   dst    = (const int*)d_in[9];
    float* out = (float*)d_out;

    cudaFuncSetAttribute(gemm_kernel<0>, cudaFuncAttributeMaxDynamicSharedMemorySize, SM_TOT);
    cudaFuncSetAttribute(gemm_kernel<1>, cudaFuncAttributeMaxDynamicSharedMemorySize, SM_TOT);
    cudaFuncSetAttribute(gemm_kernel<2>, cudaFuncAttributeMaxDynamicSharedMemorySize, SM_TOT);

    float* g_h_p;    cudaGetSymbolAddress((void**)&g_h_p, g_h);
    float* g_t_p;    cudaGetSymbolAddress((void**)&g_t_p, g_t);

    const int gemm_grid = (N_NODES + BM - 1) / BM;   // 391
    const int edge_grid = (N_EDGES * 24 + 255) / 256;

    // 1) h = gelu(x_feat @ W_pre + b_pre); zero aggr
    gemm_kernel<0><<<gemm_grid, 256, SM_TOT>>>(x_feat, W_pre, b_pre, g_h_p);
    // 2) aggr[dst] += h[src] * bases
    edge_kernel<<<edge_grid, 256>>>(bases, src, dst);
    // 3) x = x_feat + aggr (persisted); t = gelu(x @ W1 + b1)
    gemm_kernel<1><<<gemm_grid, 256, SM_TOT>>>(x_feat, W1, b1, g_t_p);
    // 4) out = x + gelu(t @ W2 + b2)
    gemm_kernel<2><<<gemm_grid, 256, SM_TOT>>>(g_t_p, W2, b2, out);
}